// round 12
// baseline (speedup 1.0000x reference)
#include <cuda_runtime.h>
#include <cuda_fp16.h>

// ---------------------------------------------------------------------------
// SlabAttention: B=16, N=4096, C=384, H=12, hd=32, BH=192
// Round 11 (= round 10 resubmit after infra failure):
// fuse x fp32->fp16 cvt into qkv A-load (kills cvt_x pass);
// kv_kernel smem aliasing (sacc reuses sk/sv) for occupancy.
// ---------------------------------------------------------------------------

#define BATCH   16
#define NTOK    4096
#define CDIM    384
#define HEADS   12
#define HD      32
#define BH_TOT  (BATCH*HEADS)      // 192
#define M_TOT   (BATCH*NTOK)       // 65536
#define EPS     1e-6f

#define BK   32
#define LDH  40    // halfs per smem row: 32 + 8 pad (80B stride)
                   // ldmatrix phase: chunk = (row*5 + col/8) mod 8, 5 coprime 8
                   // -> 8 consecutive rows hit 8 distinct 16B columns: conflict-free

// scratch (device globals; allocation-free rule)
__device__ alignas(256) __half g_wqkv [(size_t)3 * CDIM * CDIM];
__device__ alignas(256) __half g_wproj[(size_t)CDIM * CDIM];
__device__ alignas(256) __half g_qh   [(size_t)BH_TOT * NTOK * HD];
__device__ alignas(256) __half g_kh   [(size_t)BH_TOT * NTOK * HD];
__device__ alignas(256) __half g_vh   [(size_t)BH_TOT * NTOK * HD];
__device__ alignas(256) __half g_preh [(size_t)M_TOT * CDIM];
__device__ float  g_ksum [BH_TOT * HD];
__device__ float  g_kv   [BH_TOT * HD * HD];

__device__ __forceinline__ void mma_f16(float* c, const unsigned* A, const unsigned* B) {
    asm volatile(
        "mma.sync.aligned.m16n8k16.row.col.f32.f16.f16.f32 "
        "{%0,%1,%2,%3},{%4,%5,%6,%7},{%8,%9},{%0,%1,%2,%3};\n"
        : "+f"(c[0]), "+f"(c[1]), "+f"(c[2]), "+f"(c[3])
        : "r"(A[0]), "r"(A[1]), "r"(A[2]), "r"(A[3]), "r"(B[0]), "r"(B[1]));
}

__device__ __forceinline__ void ldsm_x4(unsigned* r, unsigned addr) {
    asm volatile("ldmatrix.sync.aligned.m8n8.x4.shared.b16 {%0,%1,%2,%3}, [%4];\n"
        : "=r"(r[0]), "=r"(r[1]), "=r"(r[2]), "=r"(r[3]) : "r"(addr));
}

__device__ __forceinline__ void cp16h(__half* smem, const __half* g) {
    unsigned saddr = (unsigned)__cvta_generic_to_shared(smem);
    asm volatile("cp.async.cg.shared.global [%0], [%1], 16;\n" :: "r"(saddr), "l"(g));
}
#define CP_COMMIT  asm volatile("cp.async.commit_group;\n")
#define CP_WAIT(n) asm volatile("cp.async.wait_group %0;\n" :: "n"(n))

// smem: 3 stages x (A 128 + B 128 rows) x LDH halfs x 2B = 61440
#define GEMM_SMEM (6 * 128 * LDH * 2)

// pack 4 half2 into a uint4 for STS.128
union Pk4 { __half2 h2[4]; uint4 u4; };

// ---------------------------------------------------------------------------
// cvt_w_zero: weight fp32->fp16 + kv/ksum zeroing (one small kernel)
// ---------------------------------------------------------------------------
__global__ __launch_bounds__(256) void cvt_w_zero(const float* __restrict__ qkv_w,
                                                  const float* __restrict__ proj_w)
{
    const int i = blockIdx.x * 256 + threadIdx.x;            // < 589824
    if (i < 3 * CDIM * CDIM) g_wqkv[i] = __float2half_rn(qkv_w[i]);
    else g_wproj[i - 3 * CDIM * CDIM] = __float2half_rn(proj_w[i - 3 * CDIM * CDIM]);
    if (i < BH_TOT * HD * HD) g_kv[i] = 0.f;
    if (i < BH_TOT * HD)      g_ksum[i] = 0.f;
}

// ---------------------------------------------------------------------------
// Shared GEMM pieces: BM=128, BN=128, BK=32, 256 thr (8 warps 2Mx4N),
// warp tile 64x32, 3-stage pipeline.
// ---------------------------------------------------------------------------
#define GEMM_PROLOGUE()                                                         \
    extern __shared__ __half smh[];                                             \
    __half* As[3] = { smh, smh + 128*LDH, smh + 2*128*LDH };                    \
    __half* Bs[3] = { smh + 3*128*LDH, smh + 4*128*LDH, smh + 5*128*LDH };      \
    const int tid  = threadIdx.x;                                               \
    const int mB   = blockIdx.y * 128;                                          \
    const int jB   = blockIdx.x * 128;                                          \
    const int lane = tid & 31;                                                  \
    const int warp = tid >> 5;                                                  \
    const int g    = lane >> 2;                                                 \
    const int t    = lane & 3;                                                  \
    const int wM   = (warp & 1) * 64;                                           \
    const int wN   = (warp >> 1) * 32;                                          \
    const int li   = lane & 7;                                                  \
    const int seg  = lane >> 3;                                                 \
    int aoff[4], boff[2];                                                       \
    _Pragma("unroll")                                                           \
    for (int mt = 0; mt < 4; mt++)                                              \
        aoff[mt] = (wM + mt*16 + li + (seg & 1)*8) * LDH + (seg >> 1)*8;        \
    _Pragma("unroll")                                                           \
    for (int np = 0; np < 2; np++)                                              \
        boff[np] = (wN + np*16 + li + (seg >> 1)*8) * LDH + (seg & 1)*8;        \
    float acc[4][4][4];                                                         \
    _Pragma("unroll")                                                           \
    for (int i = 0; i < 4; i++)                                                 \
        _Pragma("unroll")                                                       \
        for (int j = 0; j < 4; j++)                                             \
            _Pragma("unroll")                                                   \
            for (int l = 0; l < 4; l++) acc[i][j][l] = 0.f;

// compute phase on stage s (common)
#define GEMM_COMPUTE(s)                                                         \
    {                                                                           \
        const unsigned uA = (unsigned)__cvta_generic_to_shared(As[s]);          \
        const unsigned uB = (unsigned)__cvta_generic_to_shared(Bs[s]);          \
        _Pragma("unroll")                                                       \
        for (int ks = 0; ks < BK; ks += 16) {                                   \
            unsigned a[4][4], bb[2][4];                                         \
            _Pragma("unroll")                                                   \
            for (int mt = 0; mt < 4; mt++)                                      \
                ldsm_x4(a[mt], uA + 2u * (unsigned)(aoff[mt] + ks));            \
            _Pragma("unroll")                                                   \
            for (int np = 0; np < 2; np++)                                      \
                ldsm_x4(bb[np], uB + 2u * (unsigned)(boff[np] + ks));           \
            _Pragma("unroll")                                                   \
            for (int mt = 0; mt < 4; mt++)                                      \
                _Pragma("unroll")                                               \
                for (int nt = 0; nt < 4; nt++)                                  \
                    mma_f16(acc[mt][nt], a[mt], &bb[nt >> 1][(nt & 1) * 2]);    \
        }                                                                       \
    }

// ---------------------------------------------------------------------------
// Kernel 1: qkv GEMM (M=65536, Nout=1152, K=384), fp16 mma, fused x-cvt.
// A loaded as fp32 (LDG) -> cvt -> STS; B via cp.async fp16.
// ---------------------------------------------------------------------------
__global__ __launch_bounds__(256) void qkv_gemm(const float* __restrict__ xp,
                                                const float* __restrict__ pos)
{
    GEMM_PROLOGUE()

    const int arow = tid >> 1;          // 0..127
    const int asg  = tid & 1;           // half-row segment (16 halfs)

#define QKV_LOAD_B(s, k0)                                                       \
    {                                                                           \
        const int c0 = tid & 511;                                               \
        cp16h(&Bs[s][(c0>>2)*LDH + (c0&3)*8],                                   \
              &g_wqkv[(size_t)(jB + (c0>>2))*CDIM + (k0) + (c0&3)*8]);          \
        const int c1 = (tid + 256) & 511;                                       \
        cp16h(&Bs[s][(c1>>2)*LDH + (c1&3)*8],                                   \
              &g_wqkv[(size_t)(jB + (c1>>2))*CDIM + (k0) + (c1&3)*8]);          \
        CP_COMMIT;                                                              \
    }

#define QKV_LDG_A(fv, k0)                                                       \
    _Pragma("unroll")                                                           \
    for (int i = 0; i < 4; i++)                                                 \
        fv[i] = *(const float4*)&xp[(size_t)(mB + arow)*CDIM + (k0) +           \
                                    asg*16 + i*4];

#define QKV_STS_A(fv, s)                                                        \
    {                                                                           \
        Pk4 p0, p1;                                                             \
        p0.h2[0] = __floats2half2_rn(fv[0].x, fv[0].y);                         \
        p0.h2[1] = __floats2half2_rn(fv[0].z, fv[0].w);                         \
        p0.h2[2] = __floats2half2_rn(fv[1].x, fv[1].y);                         \
        p0.h2[3] = __floats2half2_rn(fv[1].z, fv[1].w);                         \
        p1.h2[0] = __floats2half2_rn(fv[2].x, fv[2].y);                         \
        p1.h2[1] = __floats2half2_rn(fv[2].z, fv[2].w);                         \
        p1.h2[2] = __floats2half2_rn(fv[3].x, fv[3].y);                         \
        p1.h2[3] = __floats2half2_rn(fv[3].z, fv[3].w);                         \
        *(uint4*)&As[s][arow*LDH + asg*16]     = p0.u4;                         \
        *(uint4*)&As[s][arow*LDH + asg*16 + 8] = p1.u4;                         \
    }

    // prologue: stages 0,1
    {
        float4 f[4];
        QKV_LDG_A(f, 0);  QKV_STS_A(f, 0);  QKV_LOAD_B(0, 0);
        QKV_LDG_A(f, BK); QKV_STS_A(f, 1);  QKV_LOAD_B(1, BK);
    }
    int s = 0;
    for (int k0 = 0; k0 < CDIM; k0 += BK) {
        if (k0 + BK < CDIM) CP_WAIT(1); else CP_WAIT(0);
        __syncthreads();
        const bool pf = (k0 + 2*BK < CDIM);
        const int  sn = (s + 2 >= 3) ? s - 1 : s + 2;
        float4 f[4];
        if (pf) {
            QKV_LDG_A(f, k0 + 2*BK);     // issue LDGs; latency hides under MMAs
            QKV_LOAD_B(sn, k0 + 2*BK);
        }
        GEMM_COMPUTE(s)
        if (pf) QKV_STS_A(f, sn);        // convert + store after compute
        __syncthreads();
        s = (s + 1 >= 3) ? 0 : s + 1;
    }
#undef QKV_LOAD_B
#undef QKV_LDG_A
#undef QKV_STS_A

    const int part = jB / CDIM;                 // 0=q, 1=k, 2=v (uniform/block)
#pragma unroll
    for (int mt = 0; mt < 4; mt++) {
#pragma unroll
        for (int nt = 0; nt < 4; nt++) {
            const int j = jB + wN + nt * 8 + 2 * t;
            const int c = j - part * CDIM;
            const int h = c >> 5;
            const int d = c & 31;
#pragma unroll
            for (int hh = 0; hh < 2; hh++) {
                const int m = mB + wM + mt * 16 + g + hh * 8;
                const int b_ = m >> 12;
                const int n  = m & 4095;
                float v0 = acc[mt][nt][hh * 2 + 0];
                float v1 = acc[mt][nt][hh * 2 + 1];
                const size_t o = (((size_t)(b_ * HEADS + h)) * NTOK + n) * HD + d;
                if (part == 0) {
                    *(__half2*)&g_qh[o] =
                        __floats2half2_rn(fmaxf(v0, 0.f), fmaxf(v1, 0.f));
                } else if (part == 1) {
                    v0 = fmaxf(v0 + pos[(size_t)n * CDIM + c],     0.f);
                    v1 = fmaxf(v1 + pos[(size_t)n * CDIM + c + 1], 0.f);
                    *(__half2*)&g_kh[o] = __floats2half2_rn(v0, v1);
                } else {
                    *(__half2*)&g_vh[o] = __floats2half2_rn(v0, v1);
                }
            }
        }
    }
}

// ---------------------------------------------------------------------------
// Kernel 2: kv[bh,c,d] += sum_{chunk} k*v ; ksum fused. grid (192, 8).
// sacc aliases sk/sv (dead after mainloop) -> smem 34KB -> 17.4KB.
// ---------------------------------------------------------------------------
__global__ __launch_bounds__(256) void kv_kernel()
{
    const int bh  = blockIdx.x;
    const int j0s = blockIdx.y * 512;
    const int tid = threadIdx.x;
    const int g   = tid >> 6;           // row group 0..3
    const int cq  = (tid >> 3) & 7;     // c quad 0..7
    const int dq  = tid & 7;            // d quad 0..7
    const int d32 = tid & 31;
    const int gr8 = tid >> 5;
    __shared__ float sbuf[4096];        // sk=[0:2048), sv=[2048:4096); later sacc
    __shared__ float sred[256];
    float* sk = sbuf;
    float* sv = sbuf + 2048;
    const size_t base = (size_t)bh * NTOK * HD;
    float acc[4][4];
#pragma unroll
    for (int i = 0; i < 4; i++)
#pragma unroll
        for (int j = 0; j < 4; j++) acc[i][j] = 0.f;
    float ksacc = 0.f;

    for (int j0 = j0s; j0 < j0s + 512; j0 += 64) {
        for (int i = tid; i < 512; i += 256) {
            const size_t gi = base + (size_t)j0 * HD + i * 4;
            float2 k01 = __half22float2(*(const __half2*)&g_kh[gi]);
            float2 k23 = __half22float2(*(const __half2*)&g_kh[gi + 2]);
            float2 v01 = __half22float2(*(const __half2*)&g_vh[gi]);
            float2 v23 = __half22float2(*(const __half2*)&g_vh[gi + 2]);
            *(float4*)&sk[i * 4] = make_float4(k01.x, k01.y, k23.x, k23.y);
            *(float4*)&sv[i * 4] = make_float4(v01.x, v01.y, v23.x, v23.y);
        }
        __syncthreads();
#pragma unroll
        for (int rr = 0; rr < 16; rr++) {
            const int r = rr * 4 + g;
            float4 kk = *(const float4*)&sk[r * 32 + cq * 4];
            float4 vv = *(const float4*)&sv[r * 32 + dq * 4];
            acc[0][0] += kk.x * vv.x; acc[0][1] += kk.x * vv.y;
            acc[0][2] += kk.x * vv.z; acc[0][3] += kk.x * vv.w;
            acc[1][0] += kk.y * vv.x; acc[1][1] += kk.y * vv.y;
            acc[1][2] += kk.y * vv.z; acc[1][3] += kk.y * vv.w;
            acc[2][0] += kk.z * vv.x; acc[2][1] += kk.z * vv.y;
            acc[2][2] += kk.z * vv.z; acc[2][3] += kk.z * vv.w;
            acc[3][0] += kk.w * vv.x; acc[3][1] += kk.w * vv.y;
            acc[3][2] += kk.w * vv.z; acc[3][3] += kk.w * vv.w;
        }
#pragma unroll
        for (int r8 = 0; r8 < 8; r8++) ksacc += sk[(gr8 + r8 * 8) * 32 + d32];
        __syncthreads();   // also orders last sk/sv reads before sacc aliasing
    }

    // group partials into aliased sbuf (sacc[g][1024]), then cross-group sum
#pragma unroll
    for (int i = 0; i < 4; i++)
        *(float4*)&sbuf[g * 1024 + (cq * 4 + i) * 32 + dq * 4] =
            make_float4(acc[i][0], acc[i][1], acc[i][2], acc[i][3]);
    sred[tid] = ksacc;
    __syncthreads();
    {
        float4 a0 = *(const float4*)&sbuf[0 * 1024 + tid * 4];
        float4 a1 = *(const float4*)&sbuf[1 * 1024 + tid * 4];
        float4 a2 = *(const float4*)&sbuf[2 * 1024 + tid * 4];
        float4 a3 = *(const float4*)&sbuf[3 * 1024 + tid * 4];
        atomicAdd(&g_kv[bh * 1024 + tid * 4 + 0], a0.x + a1.x + a2.x + a3.x);
        atomicAdd(&g_kv[bh * 1024 + tid * 4 + 1], a0.y + a1.y + a2.y + a3.y);
        atomicAdd(&g_kv[bh * 1024 + tid * 4 + 2], a0.z + a1.z + a2.z + a3.z);
        atomicAdd(&g_kv[bh * 1024 + tid * 4 + 3], a0.w + a1.w + a2.w + a3.w);
    }
    if (gr8 == 0) {
        float ssum = 0.f;
#pragma unroll
        for (int gg = 0; gg < 8; gg++) ssum += sred[gg * 32 + d32];
        atomicAdd(&g_ksum[bh * HD + d32], ssum);
    }
}

// ---------------------------------------------------------------------------
// Kernel 4: attn_out (unchanged).
// ---------------------------------------------------------------------------
#define SV_ROW (68 * 32)
#define ATTN_SMEM (5*SV_ROW*2 + (2048 + 1024 + 800 + 32) * 4)

__global__ __launch_bounds__(256, 4) void attn_out(const float* __restrict__ dwc_w,
                                                   const float* __restrict__ dwc_b)
{
    extern __shared__ float sm[];
    __half* svh = (__half*)sm;                  // 5 * SV_ROW halfs
    float* sq  = sm + (5 * SV_ROW * 2) / 4;     // 2048 floats
    float* skv = sq + 2048;                     // 1024
    float* sw  = skv + 1024;                    // 800
    float* sks = sw + 800;                      // 32

    const int y  = blockIdx.x;
    const int bh = blockIdx.y;
    const int tid = threadIdx.x;
    const int d  = tid & 31;
    const int gr = tid >> 5;
    const int x0 = gr * 8;
    const size_t base = (size_t)bh * NTOK * HD;

    for (int i = tid; i < 5 * 4 * 32; i += 256) {
        const int row = i >> 7;
        const int rem = i & 127;
        const int col = rem >> 5;
        const int dd  = rem & 31;
        const int xc  = (col < 2) ? col : (64 + col);
        svh[row * SV_ROW + xc * 32 + dd] = __float2half(0.f);
    }
#pragma unroll
    for (int ky = 0; ky < 5; ky++) {
        const int yy = y + ky - 2;
        for (int c = tid; c < 512; c += 256) {
            const int x = c >> 3, dq = (c & 7) * 4;
            uint2 val = make_uint2(0u, 0u);
            if ((unsigned)yy < 64u)
                val = *(const uint2*)&g_vh[base + ((size_t)(yy * 64 + x)) * HD + dq];
            *(uint2*)&svh[ky * SV_ROW + (x + 2) * 32 + dq] = val;
        }
    }
    for (int c = tid; c < 512; c += 256) {
        const int x = c >> 3, dq = (c & 7) * 4;
        const size_t gi = base + ((size_t)(y * 64 + x)) * HD + dq;
        float2 a = __half22float2(*(const __half2*)&g_qh[gi]);
        float2 bq = __half22float2(*(const __half2*)&g_qh[gi + 2]);
        *(float4*)&sq[x * 32 + dq] = make_float4(a.x, a.y, bq.x, bq.y);
    }
    *(float4*)&skv[tid * 4] = *(const float4*)&g_kv[bh * 1024 + tid * 4];
    for (int i = tid; i < 800; i += 256) sw[i] = dwc_w[i];
    if (tid < 32) sks[tid] = g_ksum[bh * HD + tid];
    __syncthreads();

    float rkv[32];
#pragma unroll
    for (int c = 0; c < 32; c++) rkv[c] = skv[c * 32 + d];
    const float rks = sks[d];
    const float rb  = dwc_b[d];

    float acc[8];
#pragma unroll
    for (int xi = 0; xi < 8; xi++) acc[xi] = rb;
#pragma unroll
    for (int ky = 0; ky < 5; ky++) {
        float w[12];
#pragma unroll
        for (int j = 0; j < 12; j++)
            w[j] = __half2float(svh[ky * SV_ROW + (x0 + j) * 32 + d]);
#pragma unroll
        for (int kx = 0; kx < 5; kx++) {
            const float cf = sw[d * 25 + ky * 5 + kx];
#pragma unroll
            for (int xi = 0; xi < 8; xi++) acc[xi] += cf * w[xi + kx];
        }
    }

    const int b_ = bh / HEADS, h = bh % HEADS;
#pragma unroll
    for (int xi = 0; xi < 8; xi++) {
        const int tok = x0 + xi;
        float o = 0.f;
#pragma unroll
        for (int c = 0; c < 32; c++) o += sq[tok * 32 + c] * rkv[c];
        float p = sq[tok * 32 + d] * rks;
#pragma unroll
        for (int off = 16; off; off >>= 1) p += __shfl_xor_sync(0xffffffffu, p, off);
        const float z = 1.f / (p + EPS);
        const int n = y * 64 + tok;
        g_preh[((size_t)(b_ * NTOK + n)) * CDIM + h * HD + d] =
            __float2half_rn(o * z + acc[xi]);
    }
}

// ---------------------------------------------------------------------------
// Kernel 5: proj GEMM (M=65536, Nout=384, K=384) + bias -> out (fp32).
// Pure-fp16 cp.async 3-stage pipeline (round-8 proven core).
// ---------------------------------------------------------------------------
__global__ __launch_bounds__(256) void proj_gemm(const float* __restrict__ bias,
                                                 float* __restrict__ out)
{
    GEMM_PROLOGUE()

#define PRJ_LOAD(s, k0)                                                         \
    {                                                                           \
        const int c0 = tid, c1 = tid + 256;                                     \
        cp16h(&As[s][(c0>>2)*LDH + (c0&3)*8],                                   \
              &g_preh[(size_t)(mB + (c0>>2))*CDIM + (k0) + (c0&3)*8]);          \
        cp16h(&Bs[s][(c0>>2)*LDH + (c0&3)*8],                                   \
              &g_wproj[(size_t)(jB + (c0>>2))*CDIM + (k0) + (c0&3)*8]);         \
        cp16h(&As[s][(c1>>2)*LDH + (c1&3)*8],                                   \
              &g_preh[(size_t)(mB + (c1>>2))*CDIM + (k0) + (c1&3)*8]);          \
        cp16h(&Bs[s][(c1>>2)*LDH + (c1&3)*8],                                   \
              &g_wproj[(size_t)(jB + (c1>>2))*CDIM + (k0) + (c1&3)*8]);         \
        CP_COMMIT;                                                              \
    }

    PRJ_LOAD(0, 0);
    PRJ_LOAD(1, BK);
    int s = 0;
    for (int k0 = 0; k0 < CDIM; k0 += BK) {
        if (k0 + BK < CDIM) CP_WAIT(1); else CP_WAIT(0);
        __syncthreads();
        if (k0 + 2*BK < CDIM) {
            const int sn = (s + 2 >= 3) ? s - 1 : s + 2;
            PRJ_LOAD(sn, k0 + 2*BK);
        }
        GEMM_COMPUTE(s)
        __syncthreads();
        s = (s + 1 >= 3) ? 0 : s + 1;
    }
#undef PRJ_LOAD

#pragma unroll
    for (int mt = 0; mt < 4; mt++) {
#pragma unroll
        for (int nt = 0; nt < 4; nt++) {
            const int j = jB + wN + nt * 8 + 2 * t;
            const float b0 = bias[j], b1 = bias[j + 1];
#pragma unroll
            for (int hh = 0; hh < 2; hh++) {
                const int m = mB + wM + mt * 16 + g + hh * 8;
                *(float2*)&out[(size_t)m * CDIM + j] =
                    make_float2(acc[mt][nt][hh * 2 + 0] + b0,
                                acc[mt][nt][hh * 2 + 1] + b1);
            }
        }
    }
}

// ---------------------------------------------------------------------------
extern "C" void kernel_launch(void* const* d_in, const int* in_sizes, int n_in,
                              void* d_out, int out_size)
{
    const float* x      = (const float*)d_in[0];
    const float* qkv_w  = (const float*)d_in[1];
    const float* pos    = (const float*)d_in[2];
    const float* dwc_w  = (const float*)d_in[3];
    const float* dwc_b  = (const float*)d_in[4];
    const float* proj_w = (const float*)d_in[5];
    const float* proj_b = (const float*)d_in[6];
    float* out = (float*)d_out;

    cudaFuncSetAttribute(qkv_gemm,  cudaFuncAttributeMaxDynamicSharedMemorySize, GEMM_SMEM);
    cudaFuncSetAttribute(proj_gemm, cudaFuncAttributeMaxDynamicSharedMemorySize, GEMM_SMEM);
    cudaFuncSetAttribute(attn_out,  cudaFuncAttributeMaxDynamicSharedMemorySize, ATTN_SMEM);

    cvt_w_zero<<<2304, 256>>>(qkv_w, proj_w);

    dim3 g1(9, M_TOT / 128);              // 1152/128 x 512
    qkv_gemm<<<g1, 256, GEMM_SMEM>>>(x, pos);

    dim3 g3(BH_TOT, 8);
    kv_kernel<<<g3, 256>>>();

    dim3 g4(64, BH_TOT);
    attn_out<<<g4, 256, ATTN_SMEM>>>(dwc_w, dwc_b);

    dim3 g5(3, M_TOT / 128);              // 384/128 x 512
    proj_gemm<<<g5, 256, GEMM_SMEM>>>(proj_b, out);
}

// round 13
// speedup vs baseline: 1.2513x; 1.2513x over previous
#include <cuda_runtime.h>
#include <cuda_fp16.h>

// ---------------------------------------------------------------------------
// SlabAttention: B=16, N=4096, C=384, H=12, hd=32, BH=192
// Round 12: revert qkv to round-8 proven form (separate cvt_x; fp16 cp.async
// A-path). Keep kv_kernel smem aliasing. rel_err bit-identical to round 8.
// ---------------------------------------------------------------------------

#define BATCH   16
#define NTOK    4096
#define CDIM    384
#define HEADS   12
#define HD      32
#define BH_TOT  (BATCH*HEADS)      // 192
#define M_TOT   (BATCH*NTOK)       // 65536
#define EPS     1e-6f

#define BK   32
#define LDH  40    // halfs per smem row: 32 + 8 pad (80B stride)
                   // ldmatrix phase: chunk = (row*5 + col/8) mod 8, 5 coprime 8
                   // -> 8 consecutive rows hit 8 distinct 16B columns: conflict-free

// scratch (device globals; allocation-free rule)
__device__ alignas(256) __half g_xh   [(size_t)M_TOT * CDIM];
__device__ alignas(256) __half g_wqkv [(size_t)3 * CDIM * CDIM];
__device__ alignas(256) __half g_wproj[(size_t)CDIM * CDIM];
__device__ alignas(256) __half g_qh   [(size_t)BH_TOT * NTOK * HD];
__device__ alignas(256) __half g_kh   [(size_t)BH_TOT * NTOK * HD];
__device__ alignas(256) __half g_vh   [(size_t)BH_TOT * NTOK * HD];
__device__ alignas(256) __half g_preh [(size_t)M_TOT * CDIM];
__device__ float  g_ksum [BH_TOT * HD];
__device__ float  g_kv   [BH_TOT * HD * HD];

__device__ __forceinline__ void mma_f16(float* c, const unsigned* A, const unsigned* B) {
    asm volatile(
        "mma.sync.aligned.m16n8k16.row.col.f32.f16.f16.f32 "
        "{%0,%1,%2,%3},{%4,%5,%6,%7},{%8,%9},{%0,%1,%2,%3};\n"
        : "+f"(c[0]), "+f"(c[1]), "+f"(c[2]), "+f"(c[3])
        : "r"(A[0]), "r"(A[1]), "r"(A[2]), "r"(A[3]), "r"(B[0]), "r"(B[1]));
}

__device__ __forceinline__ void ldsm_x4(unsigned* r, unsigned addr) {
    asm volatile("ldmatrix.sync.aligned.m8n8.x4.shared.b16 {%0,%1,%2,%3}, [%4];\n"
        : "=r"(r[0]), "=r"(r[1]), "=r"(r[2]), "=r"(r[3]) : "r"(addr));
}

__device__ __forceinline__ void cp16h(__half* smem, const __half* g) {
    unsigned saddr = (unsigned)__cvta_generic_to_shared(smem);
    asm volatile("cp.async.cg.shared.global [%0], [%1], 16;\n" :: "r"(saddr), "l"(g));
}
#define CP_COMMIT  asm volatile("cp.async.commit_group;\n")
#define CP_WAIT(n) asm volatile("cp.async.wait_group %0;\n" :: "n"(n))

// smem: 3 stages x (A 128 + B 128 rows) x LDH halfs x 2B = 61440
#define GEMM_SMEM (6 * 128 * LDH * 2)

// ---------------------------------------------------------------------------
// Conversion kernels
// ---------------------------------------------------------------------------
__global__ __launch_bounds__(256) void cvt_x(const float4* __restrict__ x)
{
    const size_t i = (size_t)blockIdx.x * 256 + threadIdx.x;
    float4 v = x[i];
    *(__half2*)&g_xh[i * 4]     = __floats2half2_rn(v.x, v.y);
    *(__half2*)&g_xh[i * 4 + 2] = __floats2half2_rn(v.z, v.w);
}

__global__ __launch_bounds__(256) void cvt_w_zero(const float* __restrict__ qkv_w,
                                                  const float* __restrict__ proj_w)
{
    const int i = blockIdx.x * 256 + threadIdx.x;            // < 589824
    if (i < 3 * CDIM * CDIM) g_wqkv[i] = __float2half_rn(qkv_w[i]);
    else g_wproj[i - 3 * CDIM * CDIM] = __float2half_rn(proj_w[i - 3 * CDIM * CDIM]);
    if (i < BH_TOT * HD * HD) g_kv[i] = 0.f;
    if (i < BH_TOT * HD)      g_ksum[i] = 0.f;
}

// ---------------------------------------------------------------------------
// GEMM core: BM=128, BN=128, BK=32, 256 thr (8 warps 2Mx4N), warp tile 64x32.
// 3-stage cp.async pipeline (2 prefetches in flight). Round-8 proven.
// ---------------------------------------------------------------------------
#define GEMM_PROLOGUE(GA, GB)                                                   \
    extern __shared__ __half smh[];                                             \
    __half* As[3] = { smh, smh + 128*LDH, smh + 2*128*LDH };                    \
    __half* Bs[3] = { smh + 3*128*LDH, smh + 4*128*LDH, smh + 5*128*LDH };      \
    const int tid  = threadIdx.x;                                               \
    const int mB   = blockIdx.y * 128;                                          \
    const int jB   = blockIdx.x * 128;                                          \
    const int lane = tid & 31;                                                  \
    const int warp = tid >> 5;                                                  \
    const int g    = lane >> 2;                                                 \
    const int t    = lane & 3;                                                  \
    const int wM   = (warp & 1) * 64;                                           \
    const int wN   = (warp >> 1) * 32;                                          \
    const int li   = lane & 7;                                                  \
    const int seg  = lane >> 3;                                                 \
    int aoff[4], boff[2];                                                       \
    _Pragma("unroll")                                                           \
    for (int mt = 0; mt < 4; mt++)                                              \
        aoff[mt] = (wM + mt*16 + li + (seg & 1)*8) * LDH + (seg >> 1)*8;        \
    _Pragma("unroll")                                                           \
    for (int np = 0; np < 2; np++)                                              \
        boff[np] = (wN + np*16 + li + (seg >> 1)*8) * LDH + (seg & 1)*8;        \
    float acc[4][4][4];                                                         \
    _Pragma("unroll")                                                           \
    for (int i = 0; i < 4; i++)                                                 \
        _Pragma("unroll")                                                       \
        for (int j = 0; j < 4; j++)                                             \
            _Pragma("unroll")                                                   \
            for (int l = 0; l < 4; l++) acc[i][j][l] = 0.f;

#define LOAD_STAGE(s, k0, GA, GB)                                               \
    {                                                                           \
        const int c0 = tid, c1 = tid + 256;                                     \
        cp16h(&As[s][(c0>>2)*LDH + (c0&3)*8],                                   \
              &GA[(size_t)(mB + (c0>>2))*CDIM + (k0) + (c0&3)*8]);              \
        cp16h(&Bs[s][(c0>>2)*LDH + (c0&3)*8],                                   \
              &GB[(size_t)(jB + (c0>>2))*CDIM + (k0) + (c0&3)*8]);              \
        cp16h(&As[s][(c1>>2)*LDH + (c1&3)*8],                                   \
              &GA[(size_t)(mB + (c1>>2))*CDIM + (k0) + (c1&3)*8]);              \
        cp16h(&Bs[s][(c1>>2)*LDH + (c1&3)*8],                                   \
              &GB[(size_t)(jB + (c1>>2))*CDIM + (k0) + (c1&3)*8]);              \
        CP_COMMIT;                                                              \
    }

// 12 iterations; stage s = iter mod 3; prefetch depth 2.
#define GEMM_MAINLOOP(GA, GB)                                                   \
    LOAD_STAGE(0, 0, GA, GB);                                                   \
    LOAD_STAGE(1, BK, GA, GB);                                                  \
    int s = 0;                                                                  \
    for (int k0 = 0; k0 < CDIM; k0 += BK) {                                     \
        if (k0 + BK < CDIM) CP_WAIT(1); else CP_WAIT(0);                        \
        __syncthreads();                                                        \
        if (k0 + 2*BK < CDIM) {                                                 \
            const int sn = (s + 2 >= 3) ? s - 1 : s + 2;                        \
            LOAD_STAGE(sn, k0 + 2*BK, GA, GB);                                  \
        }                                                                       \
        const unsigned uA = (unsigned)__cvta_generic_to_shared(As[s]);          \
        const unsigned uB = (unsigned)__cvta_generic_to_shared(Bs[s]);          \
        _Pragma("unroll")                                                       \
        for (int ks = 0; ks < BK; ks += 16) {                                   \
            unsigned a[4][4], bb[2][4];                                         \
            _Pragma("unroll")                                                   \
            for (int mt = 0; mt < 4; mt++)                                      \
                ldsm_x4(a[mt], uA + 2u * (unsigned)(aoff[mt] + ks));            \
            _Pragma("unroll")                                                   \
            for (int np = 0; np < 2; np++)                                      \
                ldsm_x4(bb[np], uB + 2u * (unsigned)(boff[np] + ks));           \
            _Pragma("unroll")                                                   \
            for (int mt = 0; mt < 4; mt++)                                      \
                _Pragma("unroll")                                               \
                for (int nt = 0; nt < 4; nt++)                                  \
                    mma_f16(acc[mt][nt], a[mt], &bb[nt >> 1][(nt & 1) * 2]);    \
        }                                                                       \
        __syncthreads();                                                        \
        s = (s + 1 >= 3) ? 0 : s + 1;                                           \
    }

// ---------------------------------------------------------------------------
// Kernel 1: qkv GEMM (M=65536, Nout=1152, K=384) + fused epilogue.
// ---------------------------------------------------------------------------
__global__ __launch_bounds__(256) void qkv_gemm(const float* __restrict__ pos)
{
    GEMM_PROLOGUE(g_xh, g_wqkv)
    GEMM_MAINLOOP(g_xh, g_wqkv)

    const int part = jB / CDIM;                 // 0=q, 1=k, 2=v (uniform/block)
#pragma unroll
    for (int mt = 0; mt < 4; mt++) {
#pragma unroll
        for (int nt = 0; nt < 4; nt++) {
            const int j = jB + wN + nt * 8 + 2 * t;
            const int c = j - part * CDIM;
            const int h = c >> 5;
            const int d = c & 31;
#pragma unroll
            for (int hh = 0; hh < 2; hh++) {
                const int m = mB + wM + mt * 16 + g + hh * 8;
                const int b_ = m >> 12;
                const int n  = m & 4095;
                float v0 = acc[mt][nt][hh * 2 + 0];
                float v1 = acc[mt][nt][hh * 2 + 1];
                const size_t o = (((size_t)(b_ * HEADS + h)) * NTOK + n) * HD + d;
                if (part == 0) {
                    *(__half2*)&g_qh[o] =
                        __floats2half2_rn(fmaxf(v0, 0.f), fmaxf(v1, 0.f));
                } else if (part == 1) {
                    v0 = fmaxf(v0 + pos[(size_t)n * CDIM + c],     0.f);
                    v1 = fmaxf(v1 + pos[(size_t)n * CDIM + c + 1], 0.f);
                    *(__half2*)&g_kh[o] = __floats2half2_rn(v0, v1);
                } else {
                    *(__half2*)&g_vh[o] = __floats2half2_rn(v0, v1);
                }
            }
        }
    }
}

// ---------------------------------------------------------------------------
// Kernel 2: kv[bh,c,d] += sum_{chunk} k*v ; ksum fused. grid (192, 8).
// sacc aliases sk/sv (dead after mainloop): smem 34KB -> 17.4KB.
// ---------------------------------------------------------------------------
__global__ __launch_bounds__(256) void kv_kernel()
{
    const int bh  = blockIdx.x;
    const int j0s = blockIdx.y * 512;
    const int tid = threadIdx.x;
    const int g   = tid >> 6;           // row group 0..3
    const int cq  = (tid >> 3) & 7;     // c quad 0..7
    const int dq  = tid & 7;            // d quad 0..7
    const int d32 = tid & 31;
    const int gr8 = tid >> 5;
    __shared__ float sbuf[4096];        // sk=[0:2048), sv=[2048:4096); later sacc
    __shared__ float sred[256];
    float* sk = sbuf;
    float* sv = sbuf + 2048;
    const size_t base = (size_t)bh * NTOK * HD;
    float acc[4][4];
#pragma unroll
    for (int i = 0; i < 4; i++)
#pragma unroll
        for (int j = 0; j < 4; j++) acc[i][j] = 0.f;
    float ksacc = 0.f;

    for (int j0 = j0s; j0 < j0s + 512; j0 += 64) {
        for (int i = tid; i < 512; i += 256) {
            const size_t gi = base + (size_t)j0 * HD + i * 4;
            float2 k01 = __half22float2(*(const __half2*)&g_kh[gi]);
            float2 k23 = __half22float2(*(const __half2*)&g_kh[gi + 2]);
            float2 v01 = __half22float2(*(const __half2*)&g_vh[gi]);
            float2 v23 = __half22float2(*(const __half2*)&g_vh[gi + 2]);
            *(float4*)&sk[i * 4] = make_float4(k01.x, k01.y, k23.x, k23.y);
            *(float4*)&sv[i * 4] = make_float4(v01.x, v01.y, v23.x, v23.y);
        }
        __syncthreads();
#pragma unroll
        for (int rr = 0; rr < 16; rr++) {
            const int r = rr * 4 + g;
            float4 kk = *(const float4*)&sk[r * 32 + cq * 4];
            float4 vv = *(const float4*)&sv[r * 32 + dq * 4];
            acc[0][0] += kk.x * vv.x; acc[0][1] += kk.x * vv.y;
            acc[0][2] += kk.x * vv.z; acc[0][3] += kk.x * vv.w;
            acc[1][0] += kk.y * vv.x; acc[1][1] += kk.y * vv.y;
            acc[1][2] += kk.y * vv.z; acc[1][3] += kk.y * vv.w;
            acc[2][0] += kk.z * vv.x; acc[2][1] += kk.z * vv.y;
            acc[2][2] += kk.z * vv.z; acc[2][3] += kk.z * vv.w;
            acc[3][0] += kk.w * vv.x; acc[3][1] += kk.w * vv.y;
            acc[3][2] += kk.w * vv.z; acc[3][3] += kk.w * vv.w;
        }
#pragma unroll
        for (int r8 = 0; r8 < 8; r8++) ksacc += sk[(gr8 + r8 * 8) * 32 + d32];
        __syncthreads();   // also orders last sk/sv reads before sacc aliasing
    }

    // group partials into aliased sbuf (sacc[g][1024]), then cross-group sum
#pragma unroll
    for (int i = 0; i < 4; i++)
        *(float4*)&sbuf[g * 1024 + (cq * 4 + i) * 32 + dq * 4] =
            make_float4(acc[i][0], acc[i][1], acc[i][2], acc[i][3]);
    sred[tid] = ksacc;
    __syncthreads();
    {
        float4 a0 = *(const float4*)&sbuf[0 * 1024 + tid * 4];
        float4 a1 = *(const float4*)&sbuf[1 * 1024 + tid * 4];
        float4 a2 = *(const float4*)&sbuf[2 * 1024 + tid * 4];
        float4 a3 = *(const float4*)&sbuf[3 * 1024 + tid * 4];
        atomicAdd(&g_kv[bh * 1024 + tid * 4 + 0], a0.x + a1.x + a2.x + a3.x);
        atomicAdd(&g_kv[bh * 1024 + tid * 4 + 1], a0.y + a1.y + a2.y + a3.y);
        atomicAdd(&g_kv[bh * 1024 + tid * 4 + 2], a0.z + a1.z + a2.z + a3.z);
        atomicAdd(&g_kv[bh * 1024 + tid * 4 + 3], a0.w + a1.w + a2.w + a3.w);
    }
    if (gr8 == 0) {
        float ssum = 0.f;
#pragma unroll
        for (int gg = 0; gg < 8; gg++) ssum += sred[gg * 32 + d32];
        atomicAdd(&g_ksum[bh * HD + d32], ssum);
    }
}

// ---------------------------------------------------------------------------
// Kernel 4: attn_out (unchanged).
// ---------------------------------------------------------------------------
#define SV_ROW (68 * 32)
#define ATTN_SMEM (5*SV_ROW*2 + (2048 + 1024 + 800 + 32) * 4)

__global__ __launch_bounds__(256, 4) void attn_out(const float* __restrict__ dwc_w,
                                                   const float* __restrict__ dwc_b)
{
    extern __shared__ float sm[];
    __half* svh = (__half*)sm;                  // 5 * SV_ROW halfs
    float* sq  = sm + (5 * SV_ROW * 2) / 4;     // 2048 floats
    float* skv = sq + 2048;                     // 1024
    float* sw  = skv + 1024;                    // 800
    float* sks = sw + 800;                      // 32

    const int y  = blockIdx.x;
    const int bh = blockIdx.y;
    const int tid = threadIdx.x;
    const int d  = tid & 31;
    const int gr = tid >> 5;
    const int x0 = gr * 8;
    const size_t base = (size_t)bh * NTOK * HD;

    for (int i = tid; i < 5 * 4 * 32; i += 256) {
        const int row = i >> 7;
        const int rem = i & 127;
        const int col = rem >> 5;
        const int dd  = rem & 31;
        const int xc  = (col < 2) ? col : (64 + col);
        svh[row * SV_ROW + xc * 32 + dd] = __float2half(0.f);
    }
#pragma unroll
    for (int ky = 0; ky < 5; ky++) {
        const int yy = y + ky - 2;
        for (int c = tid; c < 512; c += 256) {
            const int x = c >> 3, dq = (c & 7) * 4;
            uint2 val = make_uint2(0u, 0u);
            if ((unsigned)yy < 64u)
                val = *(const uint2*)&g_vh[base + ((size_t)(yy * 64 + x)) * HD + dq];
            *(uint2*)&svh[ky * SV_ROW + (x + 2) * 32 + dq] = val;
        }
    }
    for (int c = tid; c < 512; c += 256) {
        const int x = c >> 3, dq = (c & 7) * 4;
        const size_t gi = base + ((size_t)(y * 64 + x)) * HD + dq;
        float2 a = __half22float2(*(const __half2*)&g_qh[gi]);
        float2 bq = __half22float2(*(const __half2*)&g_qh[gi + 2]);
        *(float4*)&sq[x * 32 + dq] = make_float4(a.x, a.y, bq.x, bq.y);
    }
    *(float4*)&skv[tid * 4] = *(const float4*)&g_kv[bh * 1024 + tid * 4];
    for (int i = tid; i < 800; i += 256) sw[i] = dwc_w[i];
    if (tid < 32) sks[tid] = g_ksum[bh * HD + tid];
    __syncthreads();

    float rkv[32];
#pragma unroll
    for (int c = 0; c < 32; c++) rkv[c] = skv[c * 32 + d];
    const float rks = sks[d];
    const float rb  = dwc_b[d];

    float acc[8];
#pragma unroll
    for (int xi = 0; xi < 8; xi++) acc[xi] = rb;
#pragma unroll
    for (int ky = 0; ky < 5; ky++) {
        float w[12];
#pragma unroll
        for (int j = 0; j < 12; j++)
            w[j] = __half2float(svh[ky * SV_ROW + (x0 + j) * 32 + d]);
#pragma unroll
        for (int kx = 0; kx < 5; kx++) {
            const float cf = sw[d * 25 + ky * 5 + kx];
#pragma unroll
            for (int xi = 0; xi < 8; xi++) acc[xi] += cf * w[xi + kx];
        }
    }

    const int b_ = bh / HEADS, h = bh % HEADS;
#pragma unroll
    for (int xi = 0; xi < 8; xi++) {
        const int tok = x0 + xi;
        float o = 0.f;
#pragma unroll
        for (int c = 0; c < 32; c++) o += sq[tok * 32 + c] * rkv[c];
        float p = sq[tok * 32 + d] * rks;
#pragma unroll
        for (int off = 16; off; off >>= 1) p += __shfl_xor_sync(0xffffffffu, p, off);
        const float z = 1.f / (p + EPS);
        const int n = y * 64 + tok;
        g_preh[((size_t)(b_ * NTOK + n)) * CDIM + h * HD + d] =
            __float2half_rn(o * z + acc[xi]);
    }
}

// ---------------------------------------------------------------------------
// Kernel 5: proj GEMM (M=65536, Nout=384, K=384) + bias -> out (fp32).
// ---------------------------------------------------------------------------
__global__ __launch_bounds__(256) void proj_gemm(const float* __restrict__ bias,
                                                 float* __restrict__ out)
{
    GEMM_PROLOGUE(g_preh, g_wproj)
    GEMM_MAINLOOP(g_preh, g_wproj)

#pragma unroll
    for (int mt = 0; mt < 4; mt++) {
#pragma unroll
        for (int nt = 0; nt < 4; nt++) {
            const int j = jB + wN + nt * 8 + 2 * t;
            const float b0 = bias[j], b1 = bias[j + 1];
#pragma unroll
            for (int hh = 0; hh < 2; hh++) {
                const int m = mB + wM + mt * 16 + g + hh * 8;
                *(float2*)&out[(size_t)m * CDIM + j] =
                    make_float2(acc[mt][nt][hh * 2 + 0] + b0,
                                acc[mt][nt][hh * 2 + 1] + b1);
            }
        }
    }
}

// ---------------------------------------------------------------------------
extern "C" void kernel_launch(void* const* d_in, const int* in_sizes, int n_in,
                              void* d_out, int out_size)
{
    const float* x      = (const float*)d_in[0];
    const float* qkv_w  = (const float*)d_in[1];
    const float* pos    = (const float*)d_in[2];
    const float* dwc_w  = (const float*)d_in[3];
    const float* dwc_b  = (const float*)d_in[4];
    const float* proj_w = (const float*)d_in[5];
    const float* proj_b = (const float*)d_in[6];
    float* out = (float*)d_out;

    cudaFuncSetAttribute(qkv_gemm,  cudaFuncAttributeMaxDynamicSharedMemorySize, GEMM_SMEM);
    cudaFuncSetAttribute(proj_gemm, cudaFuncAttributeMaxDynamicSharedMemorySize, GEMM_SMEM);
    cudaFuncSetAttribute(attn_out,  cudaFuncAttributeMaxDynamicSharedMemorySize, ATTN_SMEM);

    cvt_x<<<24576, 256>>>((const float4*)x);
    cvt_w_zero<<<2304, 256>>>(qkv_w, proj_w);

    dim3 g1(9, M_TOT / 128);              // 1152/128 x 512
    qkv_gemm<<<g1, 256, GEMM_SMEM>>>(pos);

    dim3 g3(BH_TOT, 8);
    kv_kernel<<<g3, 256>>>();

    dim3 g4(64, BH_TOT);
    attn_out<<<g4, 256, ATTN_SMEM>>>(dwc_w, dwc_b);

    dim3 g5(3, M_TOT / 128);              // 384/128 x 512
    proj_gemm<<<g5, 256, GEMM_SMEM>>>(proj_b, out);
}

// round 16
// speedup vs baseline: 1.2582x; 1.0056x over previous
#include <cuda_runtime.h>
#include <cuda_fp16.h>

// ---------------------------------------------------------------------------
// SlabAttention: B=16, N=4096, C=384, H=12, hd=32, BH=192
// Round 14 (= round 13 resubmit after infra failure):
// attn_out MIO cut — float4 sq reads in the o-loop and cooperative
// per-block z computation (no SHFLs). GEMMs/kv/cvt frozen at round-12 state.
// ---------------------------------------------------------------------------

#define BATCH   16
#define NTOK    4096
#define CDIM    384
#define HEADS   12
#define HD      32
#define BH_TOT  (BATCH*HEADS)      // 192
#define M_TOT   (BATCH*NTOK)       // 65536
#define EPS     1e-6f

#define BK   32
#define LDH  40    // halfs per smem row: 32 + 8 pad (80B stride)
                   // ldmatrix phase: chunk = (row*5 + col/8) mod 8, 5 coprime 8
                   // -> 8 consecutive rows hit 8 distinct 16B columns: conflict-free

// scratch (device globals; allocation-free rule)
__device__ alignas(256) __half g_xh   [(size_t)M_TOT * CDIM];
__device__ alignas(256) __half g_wqkv [(size_t)3 * CDIM * CDIM];
__device__ alignas(256) __half g_wproj[(size_t)CDIM * CDIM];
__device__ alignas(256) __half g_qh   [(size_t)BH_TOT * NTOK * HD];
__device__ alignas(256) __half g_kh   [(size_t)BH_TOT * NTOK * HD];
__device__ alignas(256) __half g_vh   [(size_t)BH_TOT * NTOK * HD];
__device__ alignas(256) __half g_preh [(size_t)M_TOT * CDIM];
__device__ float  g_ksum [BH_TOT * HD];
__device__ float  g_kv   [BH_TOT * HD * HD];

__device__ __forceinline__ void mma_f16(float* c, const unsigned* A, const unsigned* B) {
    asm volatile(
        "mma.sync.aligned.m16n8k16.row.col.f32.f16.f16.f32 "
        "{%0,%1,%2,%3},{%4,%5,%6,%7},{%8,%9},{%0,%1,%2,%3};\n"
        : "+f"(c[0]), "+f"(c[1]), "+f"(c[2]), "+f"(c[3])
        : "r"(A[0]), "r"(A[1]), "r"(A[2]), "r"(A[3]), "r"(B[0]), "r"(B[1]));
}

__device__ __forceinline__ void ldsm_x4(unsigned* r, unsigned addr) {
    asm volatile("ldmatrix.sync.aligned.m8n8.x4.shared.b16 {%0,%1,%2,%3}, [%4];\n"
        : "=r"(r[0]), "=r"(r[1]), "=r"(r[2]), "=r"(r[3]) : "r"(addr));
}

__device__ __forceinline__ void cp16h(__half* smem, const __half* g) {
    unsigned saddr = (unsigned)__cvta_generic_to_shared(smem);
    asm volatile("cp.async.cg.shared.global [%0], [%1], 16;\n" :: "r"(saddr), "l"(g));
}
#define CP_COMMIT  asm volatile("cp.async.commit_group;\n")
#define CP_WAIT(n) asm volatile("cp.async.wait_group %0;\n" :: "n"(n))

// smem: 3 stages x (A 128 + B 128 rows) x LDH halfs x 2B = 61440
#define GEMM_SMEM (6 * 128 * LDH * 2)

// ---------------------------------------------------------------------------
// Conversion kernels
// ---------------------------------------------------------------------------
__global__ __launch_bounds__(256) void cvt_x(const float4* __restrict__ x)
{
    const size_t i = (size_t)blockIdx.x * 256 + threadIdx.x;
    float4 v = x[i];
    *(__half2*)&g_xh[i * 4]     = __floats2half2_rn(v.x, v.y);
    *(__half2*)&g_xh[i * 4 + 2] = __floats2half2_rn(v.z, v.w);
}

__global__ __launch_bounds__(256) void cvt_w_zero(const float* __restrict__ qkv_w,
                                                  const float* __restrict__ proj_w)
{
    const int i = blockIdx.x * 256 + threadIdx.x;            // < 589824
    if (i < 3 * CDIM * CDIM) g_wqkv[i] = __float2half_rn(qkv_w[i]);
    else g_wproj[i - 3 * CDIM * CDIM] = __float2half_rn(proj_w[i - 3 * CDIM * CDIM]);
    if (i < BH_TOT * HD * HD) g_kv[i] = 0.f;
    if (i < BH_TOT * HD)      g_ksum[i] = 0.f;
}

// ---------------------------------------------------------------------------
// GEMM core: BM=128, BN=128, BK=32, 256 thr (8 warps 2Mx4N), warp tile 64x32.
// 3-stage cp.async pipeline (2 prefetches in flight). Proven.
// ---------------------------------------------------------------------------
#define GEMM_PROLOGUE(GA, GB)                                                   \
    extern __shared__ __half smh[];                                             \
    __half* As[3] = { smh, smh + 128*LDH, smh + 2*128*LDH };                    \
    __half* Bs[3] = { smh + 3*128*LDH, smh + 4*128*LDH, smh + 5*128*LDH };      \
    const int tid  = threadIdx.x;                                               \
    const int mB   = blockIdx.y * 128;                                          \
    const int jB   = blockIdx.x * 128;                                          \
    const int lane = tid & 31;                                                  \
    const int warp = tid >> 5;                                                  \
    const int g    = lane >> 2;                                                 \
    const int t    = lane & 3;                                                  \
    const int wM   = (warp & 1) * 64;                                           \
    const int wN   = (warp >> 1) * 32;                                          \
    const int li   = lane & 7;                                                  \
    const int seg  = lane >> 3;                                                 \
    int aoff[4], boff[2];                                                       \
    _Pragma("unroll")                                                           \
    for (int mt = 0; mt < 4; mt++)                                              \
        aoff[mt] = (wM + mt*16 + li + (seg & 1)*8) * LDH + (seg >> 1)*8;        \
    _Pragma("unroll")                                                           \
    for (int np = 0; np < 2; np++)                                              \
        boff[np] = (wN + np*16 + li + (seg >> 1)*8) * LDH + (seg & 1)*8;        \
    float acc[4][4][4];                                                         \
    _Pragma("unroll")                                                           \
    for (int i = 0; i < 4; i++)                                                 \
        _Pragma("unroll")                                                       \
        for (int j = 0; j < 4; j++)                                             \
            _Pragma("unroll")                                                   \
            for (int l = 0; l < 4; l++) acc[i][j][l] = 0.f;

#define LOAD_STAGE(s, k0, GA, GB)                                               \
    {                                                                           \
        const int c0 = tid, c1 = tid + 256;                                     \
        cp16h(&As[s][(c0>>2)*LDH + (c0&3)*8],                                   \
              &GA[(size_t)(mB + (c0>>2))*CDIM + (k0) + (c0&3)*8]);              \
        cp16h(&Bs[s][(c0>>2)*LDH + (c0&3)*8],                                   \
              &GB[(size_t)(jB + (c0>>2))*CDIM + (k0) + (c0&3)*8]);              \
        cp16h(&As[s][(c1>>2)*LDH + (c1&3)*8],                                   \
              &GA[(size_t)(mB + (c1>>2))*CDIM + (k0) + (c1&3)*8]);              \
        cp16h(&Bs[s][(c1>>2)*LDH + (c1&3)*8],                                   \
              &GB[(size_t)(jB + (c1>>2))*CDIM + (k0) + (c1&3)*8]);              \
        CP_COMMIT;                                                              \
    }

// 12 iterations; stage s = iter mod 3; prefetch depth 2.
#define GEMM_MAINLOOP(GA, GB)                                                   \
    LOAD_STAGE(0, 0, GA, GB);                                                   \
    LOAD_STAGE(1, BK, GA, GB);                                                  \
    int s = 0;                                                                  \
    for (int k0 = 0; k0 < CDIM; k0 += BK) {                                     \
        if (k0 + BK < CDIM) CP_WAIT(1); else CP_WAIT(0);                        \
        __syncthreads();                                                        \
        if (k0 + 2*BK < CDIM) {                                                 \
            const int sn = (s + 2 >= 3) ? s - 1 : s + 2;                        \
            LOAD_STAGE(sn, k0 + 2*BK, GA, GB);                                  \
        }                                                                       \
        const unsigned uA = (unsigned)__cvta_generic_to_shared(As[s]);          \
        const unsigned uB = (unsigned)__cvta_generic_to_shared(Bs[s]);          \
        _Pragma("unroll")                                                       \
        for (int ks = 0; ks < BK; ks += 16) {                                   \
            unsigned a[4][4], bb[2][4];                                         \
            _Pragma("unroll")                                                   \
            for (int mt = 0; mt < 4; mt++)                                      \
                ldsm_x4(a[mt], uA + 2u * (unsigned)(aoff[mt] + ks));            \
            _Pragma("unroll")                                                   \
            for (int np = 0; np < 2; np++)                                      \
                ldsm_x4(bb[np], uB + 2u * (unsigned)(boff[np] + ks));           \
            _Pragma("unroll")                                                   \
            for (int mt = 0; mt < 4; mt++)                                      \
                _Pragma("unroll")                                               \
                for (int nt = 0; nt < 4; nt++)                                  \
                    mma_f16(acc[mt][nt], a[mt], &bb[nt >> 1][(nt & 1) * 2]);    \
        }                                                                       \
        __syncthreads();                                                        \
        s = (s + 1 >= 3) ? 0 : s + 1;                                           \
    }

// ---------------------------------------------------------------------------
// Kernel 1: qkv GEMM (M=65536, Nout=1152, K=384) + fused epilogue.
// ---------------------------------------------------------------------------
__global__ __launch_bounds__(256) void qkv_gemm(const float* __restrict__ pos)
{
    GEMM_PROLOGUE(g_xh, g_wqkv)
    GEMM_MAINLOOP(g_xh, g_wqkv)

    const int part = jB / CDIM;                 // 0=q, 1=k, 2=v (uniform/block)
#pragma unroll
    for (int mt = 0; mt < 4; mt++) {
#pragma unroll
        for (int nt = 0; nt < 4; nt++) {
            const int j = jB + wN + nt * 8 + 2 * t;
            const int c = j - part * CDIM;
            const int h = c >> 5;
            const int d = c & 31;
#pragma unroll
            for (int hh = 0; hh < 2; hh++) {
                const int m = mB + wM + mt * 16 + g + hh * 8;
                const int b_ = m >> 12;
                const int n  = m & 4095;
                float v0 = acc[mt][nt][hh * 2 + 0];
                float v1 = acc[mt][nt][hh * 2 + 1];
                const size_t o = (((size_t)(b_ * HEADS + h)) * NTOK + n) * HD + d;
                if (part == 0) {
                    *(__half2*)&g_qh[o] =
                        __floats2half2_rn(fmaxf(v0, 0.f), fmaxf(v1, 0.f));
                } else if (part == 1) {
                    v0 = fmaxf(v0 + pos[(size_t)n * CDIM + c],     0.f);
                    v1 = fmaxf(v1 + pos[(size_t)n * CDIM + c + 1], 0.f);
                    *(__half2*)&g_kh[o] = __floats2half2_rn(v0, v1);
                } else {
                    *(__half2*)&g_vh[o] = __floats2half2_rn(v0, v1);
                }
            }
        }
    }
}

// ---------------------------------------------------------------------------
// Kernel 2: kv[bh,c,d] += sum_{chunk} k*v ; ksum fused. grid (192, 8).
// ---------------------------------------------------------------------------
__global__ __launch_bounds__(256) void kv_kernel()
{
    const int bh  = blockIdx.x;
    const int j0s = blockIdx.y * 512;
    const int tid = threadIdx.x;
    const int g   = tid >> 6;           // row group 0..3
    const int cq  = (tid >> 3) & 7;     // c quad 0..7
    const int dq  = tid & 7;            // d quad 0..7
    const int d32 = tid & 31;
    const int gr8 = tid >> 5;
    __shared__ float sbuf[4096];        // sk=[0:2048), sv=[2048:4096); later sacc
    __shared__ float sred[256];
    float* sk = sbuf;
    float* sv = sbuf + 2048;
    const size_t base = (size_t)bh * NTOK * HD;
    float acc[4][4];
#pragma unroll
    for (int i = 0; i < 4; i++)
#pragma unroll
        for (int j = 0; j < 4; j++) acc[i][j] = 0.f;
    float ksacc = 0.f;

    for (int j0 = j0s; j0 < j0s + 512; j0 += 64) {
        for (int i = tid; i < 512; i += 256) {
            const size_t gi = base + (size_t)j0 * HD + i * 4;
            float2 k01 = __half22float2(*(const __half2*)&g_kh[gi]);
            float2 k23 = __half22float2(*(const __half2*)&g_kh[gi + 2]);
            float2 v01 = __half22float2(*(const __half2*)&g_vh[gi]);
            float2 v23 = __half22float2(*(const __half2*)&g_vh[gi + 2]);
            *(float4*)&sk[i * 4] = make_float4(k01.x, k01.y, k23.x, k23.y);
            *(float4*)&sv[i * 4] = make_float4(v01.x, v01.y, v23.x, v23.y);
        }
        __syncthreads();
#pragma unroll
        for (int rr = 0; rr < 16; rr++) {
            const int r = rr * 4 + g;
            float4 kk = *(const float4*)&sk[r * 32 + cq * 4];
            float4 vv = *(const float4*)&sv[r * 32 + dq * 4];
            acc[0][0] += kk.x * vv.x; acc[0][1] += kk.x * vv.y;
            acc[0][2] += kk.x * vv.z; acc[0][3] += kk.x * vv.w;
            acc[1][0] += kk.y * vv.x; acc[1][1] += kk.y * vv.y;
            acc[1][2] += kk.y * vv.z; acc[1][3] += kk.y * vv.w;
            acc[2][0] += kk.z * vv.x; acc[2][1] += kk.z * vv.y;
            acc[2][2] += kk.z * vv.z; acc[2][3] += kk.z * vv.w;
            acc[3][0] += kk.w * vv.x; acc[3][1] += kk.w * vv.y;
            acc[3][2] += kk.w * vv.z; acc[3][3] += kk.w * vv.w;
        }
#pragma unroll
        for (int r8 = 0; r8 < 8; r8++) ksacc += sk[(gr8 + r8 * 8) * 32 + d32];
        __syncthreads();   // also orders last sk/sv reads before sacc aliasing
    }

    // group partials into aliased sbuf (sacc[g][1024]), then cross-group sum
#pragma unroll
    for (int i = 0; i < 4; i++)
        *(float4*)&sbuf[g * 1024 + (cq * 4 + i) * 32 + dq * 4] =
            make_float4(acc[i][0], acc[i][1], acc[i][2], acc[i][3]);
    sred[tid] = ksacc;
    __syncthreads();
    {
        float4 a0 = *(const float4*)&sbuf[0 * 1024 + tid * 4];
        float4 a1 = *(const float4*)&sbuf[1 * 1024 + tid * 4];
        float4 a2 = *(const float4*)&sbuf[2 * 1024 + tid * 4];
        float4 a3 = *(const float4*)&sbuf[3 * 1024 + tid * 4];
        atomicAdd(&g_kv[bh * 1024 + tid * 4 + 0], a0.x + a1.x + a2.x + a3.x);
        atomicAdd(&g_kv[bh * 1024 + tid * 4 + 1], a0.y + a1.y + a2.y + a3.y);
        atomicAdd(&g_kv[bh * 1024 + tid * 4 + 2], a0.z + a1.z + a2.z + a3.z);
        atomicAdd(&g_kv[bh * 1024 + tid * 4 + 3], a0.w + a1.w + a2.w + a3.w);
    }
    if (gr8 == 0) {
        float ssum = 0.f;
#pragma unroll
        for (int gg = 0; gg < 8; gg++) ssum += sred[gg * 32 + d32];
        atomicAdd(&g_ksum[bh * HD + d32], ssum);
    }
}

// ---------------------------------------------------------------------------
// Kernel 4: attn_out v3. Block = one y-row (64 tokens x 32 ch) of one bh.
// MIO cuts: (a) z[tok] computed once per block cooperatively (no SHFLs),
// (b) o-loop reads sq via broadcast LDS.128 (8 loads/token instead of 32).
// ---------------------------------------------------------------------------
#define SV_ROW (68 * 32)
// floats: sq 2048, skv 1024, sw 800, sks 32, spz 256, sz 64 ; halfs: 5*SV_ROW
#define ATTN_SMEM (5*SV_ROW*2 + (2048 + 1024 + 800 + 32 + 256 + 64) * 4)

__global__ __launch_bounds__(256, 4) void attn_out(const float* __restrict__ dwc_w,
                                                   const float* __restrict__ dwc_b)
{
    extern __shared__ float sm[];
    __half* svh = (__half*)sm;                  // 5 * SV_ROW halfs
    float* sq  = sm + (5 * SV_ROW * 2) / 4;     // 2048 floats
    float* skv = sq + 2048;                     // 1024
    float* sw  = skv + 1024;                    // 800
    float* sks = sw + 800;                      // 32
    float* spz = sks + 32;                      // 256
    float* sz  = spz + 256;                     // 64

    const int y  = blockIdx.x;
    const int bh = blockIdx.y;
    const int tid = threadIdx.x;
    const int d  = tid & 31;
    const int gr = tid >> 5;
    const int x0 = gr * 8;
    const size_t base = (size_t)bh * NTOK * HD;

    for (int i = tid; i < 5 * 4 * 32; i += 256) {
        const int row = i >> 7;
        const int rem = i & 127;
        const int col = rem >> 5;
        const int dd  = rem & 31;
        const int xc  = (col < 2) ? col : (64 + col);
        svh[row * SV_ROW + xc * 32 + dd] = __float2half(0.f);
    }
#pragma unroll
    for (int ky = 0; ky < 5; ky++) {
        const int yy = y + ky - 2;
        for (int c = tid; c < 512; c += 256) {
            const int x = c >> 3, dq = (c & 7) * 4;
            uint2 val = make_uint2(0u, 0u);
            if ((unsigned)yy < 64u)
                val = *(const uint2*)&g_vh[base + ((size_t)(yy * 64 + x)) * HD + dq];
            *(uint2*)&svh[ky * SV_ROW + (x + 2) * 32 + dq] = val;
        }
    }
    for (int c = tid; c < 512; c += 256) {
        const int x = c >> 3, dq = (c & 7) * 4;
        const size_t gi = base + ((size_t)(y * 64 + x)) * HD + dq;
        float2 a = __half22float2(*(const __half2*)&g_qh[gi]);
        float2 bq = __half22float2(*(const __half2*)&g_qh[gi + 2]);
        *(float4*)&sq[x * 32 + dq] = make_float4(a.x, a.y, bq.x, bq.y);
    }
    *(float4*)&skv[tid * 4] = *(const float4*)&g_kv[bh * 1024 + tid * 4];
    for (int i = tid; i < 800; i += 256) sw[i] = dwc_w[i];
    if (tid < 32) sks[tid] = g_ksum[bh * HD + tid];
    __syncthreads();

    // cooperative z: 64 tokens x 4 partials (8 c's each), then combine
    {
        const int tok = tid >> 2, part = tid & 3;
        const int c8 = part * 8;
        float4 q0 = *(const float4*)&sq[tok * 32 + c8];
        float4 q1 = *(const float4*)&sq[tok * 32 + c8 + 4];
        float p = q0.x * sks[c8 + 0] + q0.y * sks[c8 + 1]
                + q0.z * sks[c8 + 2] + q0.w * sks[c8 + 3]
                + q1.x * sks[c8 + 4] + q1.y * sks[c8 + 5]
                + q1.z * sks[c8 + 6] + q1.w * sks[c8 + 7];
        spz[tid] = p;
    }
    __syncthreads();
    if (tid < 64)
        sz[tid] = 1.f / (spz[tid * 4] + spz[tid * 4 + 1] +
                         spz[tid * 4 + 2] + spz[tid * 4 + 3] + EPS);
    __syncthreads();

    float rkv[32];
#pragma unroll
    for (int c = 0; c < 32; c++) rkv[c] = skv[c * 32 + d];
    const float rb  = dwc_b[d];

    // depthwise 5x5, 8 outputs per thread, sliding window
    float acc[8];
#pragma unroll
    for (int xi = 0; xi < 8; xi++) acc[xi] = rb;
#pragma unroll
    for (int ky = 0; ky < 5; ky++) {
        float w[12];
#pragma unroll
        for (int j = 0; j < 12; j++)
            w[j] = __half2float(svh[ky * SV_ROW + (x0 + j) * 32 + d]);
#pragma unroll
        for (int kx = 0; kx < 5; kx++) {
            const float cf = sw[d * 25 + ky * 5 + kx];
#pragma unroll
            for (int xi = 0; xi < 8; xi++) acc[xi] += cf * w[xi + kx];
        }
    }

    const int b_ = bh / HEADS, h = bh % HEADS;
#pragma unroll
    for (int xi = 0; xi < 8; xi++) {
        const int tok = x0 + xi;
        float o = 0.f;
#pragma unroll
        for (int cq = 0; cq < 8; cq++) {
            float4 qv = *(const float4*)&sq[tok * 32 + cq * 4];
            o += qv.x * rkv[cq * 4 + 0] + qv.y * rkv[cq * 4 + 1]
               + qv.z * rkv[cq * 4 + 2] + qv.w * rkv[cq * 4 + 3];
        }
        const int n = y * 64 + tok;
        g_preh[((size_t)(b_ * NTOK + n)) * CDIM + h * HD + d] =
            __float2half_rn(o * sz[tok] + acc[xi]);
    }
}

// ---------------------------------------------------------------------------
// Kernel 5: proj GEMM (M=65536, Nout=384, K=384) + bias -> out (fp32).
// ---------------------------------------------------------------------------
__global__ __launch_bounds__(256) void proj_gemm(const float* __restrict__ bias,
                                                 float* __restrict__ out)
{
    GEMM_PROLOGUE(g_preh, g_wproj)
    GEMM_MAINLOOP(g_preh, g_wproj)

#pragma unroll
    for (int mt = 0; mt < 4; mt++) {
#pragma unroll
        for (int nt = 0; nt < 4; nt++) {
            const int j = jB + wN + nt * 8 + 2 * t;
            const float b0 = bias[j], b1 = bias[j + 1];
#pragma unroll
            for (int hh = 0; hh < 2; hh++) {
                const int m = mB + wM + mt * 16 + g + hh * 8;
                *(float2*)&out[(size_t)m * CDIM + j] =
                    make_float2(acc[mt][nt][hh * 2 + 0] + b0,
                                acc[mt][nt][hh * 2 + 1] + b1);
            }
        }
    }
}

// ---------------------------------------------------------------------------
extern "C" void kernel_launch(void* const* d_in, const int* in_sizes, int n_in,
                              void* d_out, int out_size)
{
    const float* x      = (const float*)d_in[0];
    const float* qkv_w  = (const float*)d_in[1];
    const float* pos    = (const float*)d_in[2];
    const float* dwc_w  = (const float*)d_in[3];
    const float* dwc_b  = (const float*)d_in[4];
    const float* proj_w = (const float*)d_in[5];
    const float* proj_b = (const float*)d_in[6];
    float* out = (float*)d_out;

    cudaFuncSetAttribute(qkv_gemm,  cudaFuncAttributeMaxDynamicSharedMemorySize, GEMM_SMEM);
    cudaFuncSetAttribute(proj_gemm, cudaFuncAttributeMaxDynamicSharedMemorySize, GEMM_SMEM);
    cudaFuncSetAttribute(attn_out,  cudaFuncAttributeMaxDynamicSharedMemorySize, ATTN_SMEM);

    cvt_x<<<24576, 256>>>((const float4*)x);
    cvt_w_zero<<<2304, 256>>>(qkv_w, proj_w);

    dim3 g1(9, M_TOT / 128);              // 1152/128 x 512
    qkv_gemm<<<g1, 256, GEMM_SMEM>>>(pos);

    dim3 g3(BH_TOT, 8);
    kv_kernel<<<g3, 256>>>();

    dim3 g4(64, BH_TOT);
    attn_out<<<g4, 256, ATTN_SMEM>>>(dwc_w, dwc_b);

    dim3 g5(3, M_TOT / 128);              // 384/128 x 512
    proj_gemm<<<g5, 256, GEMM_SMEM>>>(proj_b, out);
}